// round 4
// baseline (speedup 1.0000x reference)
#include <cuda_runtime.h>
#include <cuda_bf16.h>
#include <math.h>
#include <cstdint>

#define NTOK 4096
#define NEXP 8
#define CDIM 768
#define HID  3072
#define NUP  (2 * HID)            // 6144 interleaved Wg/Wi cols
#define TMR  128
#define PADN (NTOK + NEXP * TMR)  // 5120
#define MTILES (PADN / TMR)       // 40
#define QMAX 16256.0f             // 127*128

// smem layout for GEMM mainloop (pitch 80 rows, conflict-free for ldmatrix)
#define SA_H 0
#define SA_L 10240
#define SB_H 20480
#define SB_L 25600
#define SMEM_LOOP 30720
#define SMEM_UP   33792           // 128 x 66 fp32 epilogue staging

// ---------------- scratch ----------------
__device__ int g_perm[PADN];
__device__ int g_tile_expert[MTILES];
__device__ int g_sh_bits[PADN];                         // row amax of h (float bits)
__device__ float g_sx[PADN];
__device__ float g_swup[NEXP * NUP];
__device__ float g_swo[NEXP * CDIM];
__device__ __align__(128) int8_t g_xq_hi[(size_t)PADN * CDIM];
__device__ __align__(128) int8_t g_xq_lo[(size_t)PADN * CDIM];
__device__ __align__(128) int8_t g_wup_hi[(size_t)NEXP * NUP * CDIM];
__device__ __align__(128) int8_t g_wup_lo[(size_t)NEXP * NUP * CDIM];
__device__ __align__(128) int8_t g_wo_hi[(size_t)NEXP * CDIM * HID];
__device__ __align__(128) int8_t g_wo_lo[(size_t)NEXP * CDIM * HID];
__device__ __align__(128) int8_t g_hq_hi[(size_t)PADN * HID];
__device__ __align__(128) int8_t g_hq_lo[(size_t)PADN * HID];
__device__ __align__(128) float  g_h[(size_t)PADN * HID];

// ---------------- helpers ----------------
static __device__ __forceinline__ uint32_t smem_u32(const void* p) {
    uint32_t a;
    asm("{ .reg .u64 t; cvta.to.shared.u64 t, %1; cvt.u32.u64 %0, t; }" : "=r"(a) : "l"(p));
    return a;
}
static __device__ __forceinline__ void ldsm4(uint32_t* r, uint32_t a) {
    asm volatile("ldmatrix.sync.aligned.m8n8.x4.shared.b16 {%0,%1,%2,%3}, [%4];"
        : "=r"(r[0]), "=r"(r[1]), "=r"(r[2]), "=r"(r[3]) : "r"(a));
}
static __device__ __forceinline__ void imma(int* c, const uint32_t* a, uint32_t b0, uint32_t b1) {
    asm volatile("mma.sync.aligned.m16n8k32.row.col.s32.s8.s8.s32 "
        "{%0,%1,%2,%3}, {%4,%5,%6,%7}, {%8,%9}, {%0,%1,%2,%3};"
        : "+r"(c[0]), "+r"(c[1]), "+r"(c[2]), "+r"(c[3])
        : "r"(a[0]), "r"(a[1]), "r"(a[2]), "r"(a[3]), "r"(b0), "r"(b1));
}
// quantize one value against scale s: q in [-16256,16256], hi in [-127,127], lo in [-64,64]
static __device__ __forceinline__ void quant1(float v, float inv_s, int8_t& h, int8_t& l) {
    float q = rintf(v * inv_s);
    float hf = rintf(q * 0.0078125f);
    h = (int8_t)(int)hf;
    l = (int8_t)(int)(q - 128.0f * hf);
}

// ---------------------------------------------------------------------------
// route (also resets h-amax)
// ---------------------------------------------------------------------------
__global__ void route_kernel(const int* __restrict__ mapped) {
    __shared__ int cnt[NEXP];
    __shared__ int off[NEXP];
    __shared__ int fill[NEXP];
    int tid = threadIdx.x;
    if (tid < NEXP) { cnt[tid] = 0; fill[tid] = 0; }
    __syncthreads();
    for (int i = tid; i < NTOK; i += blockDim.x) atomicAdd(&cnt[mapped[i]], 1);
    __syncthreads();
    if (tid == 0) {
        int o = 0;
        for (int e = 0; e < NEXP; e++) {
            off[e] = o;
            int tiles = (cnt[e] + TMR - 1) / TMR;
            for (int t = 0; t < tiles; t++) g_tile_expert[o / TMR + t] = e;
            o += tiles * TMR;
        }
        for (int t = o / TMR; t < MTILES; t++) g_tile_expert[t] = -1;
    }
    __syncthreads();
    for (int i = tid; i < PADN; i += blockDim.x) { g_perm[i] = -1; g_sh_bits[i] = 0; }
    __syncthreads();
    for (int i = tid; i < NTOK; i += blockDim.x) {
        int e = mapped[i];
        g_perm[off[e] + atomicAdd(&fill[e], 1)] = i;
    }
}

// ---------------------------------------------------------------------------
// quantize x rows into permuted order (one CTA per padded row)
// ---------------------------------------------------------------------------
__global__ __launch_bounds__(256) void quant_x_kernel(const float* __restrict__ x) {
    int row = blockIdx.x;
    int tid = threadIdx.x;
    int prow = g_perm[row];
    __shared__ float red[8];
    __shared__ float s_inv;
    float v[3] = {0.f, 0.f, 0.f};
    if (prow >= 0) {
        const float* xr = x + (size_t)prow * CDIM;
        #pragma unroll
        for (int j = 0; j < 3; j++) v[j] = xr[tid + 256 * j];
    }
    float m = fmaxf(fmaxf(fabsf(v[0]), fabsf(v[1])), fabsf(v[2]));
    #pragma unroll
    for (int o = 16; o; o >>= 1) m = fmaxf(m, __shfl_xor_sync(~0u, m, o));
    if ((tid & 31) == 0) red[tid >> 5] = m;
    __syncthreads();
    if (tid == 0) {
        float am = red[0];
        #pragma unroll
        for (int j = 1; j < 8; j++) am = fmaxf(am, red[j]);
        float s = fmaxf(am, 1e-30f) / QMAX;
        g_sx[row] = s;
        s_inv = 1.0f / s;
    }
    __syncthreads();
    float inv = s_inv;
    #pragma unroll
    for (int j = 0; j < 3; j++) {
        int8_t h, l;
        quant1(v[j], inv, h, l);
        g_xq_hi[(size_t)row * CDIM + tid + 256 * j] = h;
        g_xq_lo[(size_t)row * CDIM + tid + 256 * j] = l;
    }
}

// ---------------------------------------------------------------------------
// quantize a 32-col block of a [K x srcN] fp32 weight matrix into
// transposed int8 rows [32][K] with per-col scales
// ---------------------------------------------------------------------------
static __device__ void quant_w_tile(const float* __restrict__ src, int srcN, int K,
                                    int8_t* __restrict__ dh, int8_t* __restrict__ dl,
                                    float* __restrict__ sdst) {
    __shared__ float red[8][32];
    __shared__ float sinv[32];
    __shared__ int8_t tb_hi[32 * 64];
    __shared__ int8_t tb_lo[32 * 64];
    int tid = threadIdx.x;
    int c = tid & 31, g = tid >> 5;

    float m = 0.f;
    for (int i = tid; i < K * 32; i += 256) {
        int k = i >> 5;
        m = fmaxf(m, fabsf(src[(size_t)k * srcN + c]));
    }
    red[g][c] = m;
    __syncthreads();
    if (tid < 32) {
        float am = red[0][tid];
        #pragma unroll
        for (int j = 1; j < 8; j++) am = fmaxf(am, red[j][tid]);
        float s = fmaxf(am, 1e-30f) / QMAX;
        sdst[tid] = s;
        sinv[tid] = 1.0f / s;
    }
    __syncthreads();

    int nchunks = K / 64;
    for (int kk = 0; kk < nchunks; kk++) {
        float inv = sinv[c];
        #pragma unroll
        for (int j = 0; j < 8; j++) {
            int k = g + 8 * j;
            float v = src[(size_t)(kk * 64 + k) * srcN + c];
            int8_t h, l;
            quant1(v, inv, h, l);
            tb_hi[c * 64 + k] = h;
            tb_lo[c * 64 + k] = l;
        }
        __syncthreads();
        int c2 = tid >> 3, g2 = tid & 7;
        *(uint2*)(dh + (size_t)c2 * K + kk * 64 + g2 * 8) = *(const uint2*)(tb_hi + c2 * 64 + g2 * 8);
        *(uint2*)(dl + (size_t)c2 * K + kk * 64 + g2 * 8) = *(const uint2*)(tb_lo + c2 * 64 + g2 * 8);
        __syncthreads();
    }
}

__global__ __launch_bounds__(256) void quant_wup_kernel(const float* __restrict__ Wg,
                                                        const float* __restrict__ Wi) {
    int cb = blockIdx.x, e = blockIdx.y, mat = blockIdx.z;
    const float* src = (mat ? Wi : Wg) + (size_t)e * CDIM * HID + cb * 32;
    int rowbase = cb * 64 + mat * 32;
    quant_w_tile(src, HID, CDIM,
                 g_wup_hi + ((size_t)e * NUP + rowbase) * CDIM,
                 g_wup_lo + ((size_t)e * NUP + rowbase) * CDIM,
                 g_swup + e * NUP + rowbase);
}

__global__ __launch_bounds__(256) void quant_wo_kernel(const float* __restrict__ Wo) {
    int cb = blockIdx.x, e = blockIdx.y;
    const float* src = Wo + (size_t)e * HID * CDIM + cb * 32;
    quant_w_tile(src, CDIM, HID,
                 g_wo_hi + ((size_t)e * CDIM + cb * 32) * HID,
                 g_wo_lo + ((size_t)e * CDIM + cb * 32) * HID,
                 g_swo + e * CDIM + cb * 32);
}

// ---------------------------------------------------------------------------
// quantize h rows (amax from atomics in up epilogue)
// ---------------------------------------------------------------------------
__global__ __launch_bounds__(256) void quant_h_kernel() {
    int row = blockIdx.x;
    int tid = threadIdx.x;
    float am = __int_as_float(g_sh_bits[row]);
    float inv = 1.0f / (fmaxf(am, 1e-30f) / QMAX);
    const float* hr = g_h + (size_t)row * HID;
    #pragma unroll
    for (int j = 0; j < 12; j++) {
        int i = tid + 256 * j;
        int8_t h, l;
        quant1(hr[i], inv, h, l);
        g_hq_hi[(size_t)row * HID + i] = h;
        g_hq_lo[(size_t)row * HID + i] = l;
    }
}

// ---------------------------------------------------------------------------
// int8 mainloop: M=128, N=64, 8 warps (4m x 2n), warp tile 32x32, k-step 64
// acc: hh (2^14 weight), mid (2^7 weight)
// ---------------------------------------------------------------------------
template<int KDIM>
static __device__ __forceinline__ void run_mainloop(
    const int8_t* __restrict__ Ah, const int8_t* __restrict__ Al,
    const int8_t* __restrict__ Bh, const int8_t* __restrict__ Bl,
    char* smem, int tid, int hh[2][4][4], int mid[2][4][4])
{
    const int NST = KDIM / 64;
    int lane = tid & 31, wid = tid >> 5;
    int wm = wid >> 1, wn = wid & 1;
    uint32_t sb = smem_u32(smem);

    int arow = tid >> 1, as0 = (tid & 1) * 2;
    const int8_t* pAh = Ah + (size_t)arow * KDIM + as0 * 16;
    const int8_t* pAl = Al + (size_t)arow * KDIM + as0 * 16;
    int sa = arow * 80 + as0 * 16;
    int brow = tid >> 2, bs = tid & 3;
    const int8_t* pBh = Bh + (size_t)brow * KDIM + bs * 16;
    const int8_t* pBl = Bl + (size_t)brow * KDIM + bs * 16;
    int sbo = brow * 80 + bs * 16;

    uint4 ra_h0 = *(const uint4*)pAh, ra_h1 = *(const uint4*)(pAh + 16);
    uint4 ra_l0 = *(const uint4*)pAl, ra_l1 = *(const uint4*)(pAl + 16);
    uint4 rb_h = *(const uint4*)pBh, rb_l = *(const uint4*)pBl;

    int t01 = (lane >> 3) & 1, t2 = lane >> 4, l7 = lane & 7;
    int a_r = (wm * 32 + t01 * 8 + l7) * 80;
    int b_r = (wn * 32 + t2 * 8 + l7) * 80;

    for (int s = 0; s < NST; s++) {
        __syncthreads();
        *(uint4*)(smem + SA_H + sa)      = ra_h0;
        *(uint4*)(smem + SA_H + sa + 16) = ra_h1;
        *(uint4*)(smem + SA_L + sa)      = ra_l0;
        *(uint4*)(smem + SA_L + sa + 16) = ra_l1;
        *(uint4*)(smem + SB_H + sbo) = rb_h;
        *(uint4*)(smem + SB_L + sbo) = rb_l;
        __syncthreads();
        if (s + 1 < NST) {
            int o = (s + 1) * 64;
            ra_h0 = *(const uint4*)(pAh + o); ra_h1 = *(const uint4*)(pAh + o + 16);
            ra_l0 = *(const uint4*)(pAl + o); ra_l1 = *(const uint4*)(pAl + o + 16);
            rb_h = *(const uint4*)(pBh + o); rb_l = *(const uint4*)(pBl + o);
        }
        #pragma unroll
        for (int kk = 0; kk < 2; kk++) {
            uint32_t af_h[2][4], af_l[2][4], bf_h[2][4], bf_l[2][4];
            int ac = kk * 32 + t2 * 16;
            int bc = kk * 32 + t01 * 16;
            #pragma unroll
            for (int mi = 0; mi < 2; mi++) {
                ldsm4(af_h[mi], sb + SA_H + a_r + mi * 16 * 80 + ac);
                ldsm4(af_l[mi], sb + SA_L + a_r + mi * 16 * 80 + ac);
            }
            #pragma unroll
            for (int p = 0; p < 2; p++) {
                ldsm4(bf_h[p], sb + SB_H + b_r + p * 16 * 80 + bc);
                ldsm4(bf_l[p], sb + SB_L + b_r + p * 16 * 80 + bc);
            }
            #pragma unroll
            for (int mi = 0; mi < 2; mi++)
                #pragma unroll
                for (int nj = 0; nj < 4; nj++) {
                    int p = nj >> 1, q = (nj & 1) * 2;
                    imma(hh[mi][nj],  af_h[mi], bf_h[p][q], bf_h[p][q + 1]);
                    imma(mid[mi][nj], af_h[mi], bf_l[p][q], bf_l[p][q + 1]);
                    imma(mid[mi][nj], af_l[mi], bf_h[p][q], bf_h[p][q + 1]);
                }
        }
    }
}

// ---------------------------------------------------------------------------
// up GEMM: A = xq [128 x 768], B = wup^T block [64 x 768]; epilogue SiLU -> h
// ---------------------------------------------------------------------------
__global__ __launch_bounds__(256, 1)
void up_gemm_kernel(const float* __restrict__ bg, const float* __restrict__ bi)
{
    extern __shared__ char smem[];
    int mtile = blockIdx.x;
    int e = g_tile_expert[mtile];
    if (e < 0) return;
    int nblk = blockIdx.y;
    int N0 = nblk * 64;
    int tid = threadIdx.x, lane = tid & 31, wid = tid >> 5;
    int wm = wid >> 1, wn = wid & 1;

    int hh[2][4][4] = {}, mid[2][4][4] = {};
    run_mainloop<CDIM>(
        g_xq_hi + (size_t)mtile * TMR * CDIM, g_xq_lo + (size_t)mtile * TMR * CDIM,
        g_wup_hi + ((size_t)e * NUP + N0) * CDIM, g_wup_lo + ((size_t)e * NUP + N0) * CDIM,
        smem, tid, hh, mid);

    __syncthreads();
    float* S = (float*)smem;
    #pragma unroll
    for (int mi = 0; mi < 2; mi++) {
        int r0 = wm * 32 + mi * 16 + (lane >> 2);
        float sa0 = g_sx[mtile * TMR + r0];
        float sa1 = g_sx[mtile * TMR + r0 + 8];
        #pragma unroll
        for (int nj = 0; nj < 4; nj++) {
            int col = wn * 32 + nj * 8 + 2 * (lane & 3);
            float sb0 = g_swup[e * NUP + N0 + col];
            float sb1 = g_swup[e * NUP + N0 + col + 1];
            S[r0 * 66 + col]           = sa0 * sb0 * (16384.f * hh[mi][nj][0] + 128.f * mid[mi][nj][0]);
            S[r0 * 66 + col + 1]       = sa0 * sb1 * (16384.f * hh[mi][nj][1] + 128.f * mid[mi][nj][1]);
            S[(r0 + 8) * 66 + col]     = sa1 * sb0 * (16384.f * hh[mi][nj][2] + 128.f * mid[mi][nj][2]);
            S[(r0 + 8) * 66 + col + 1] = sa1 * sb1 * (16384.f * hh[mi][nj][3] + 128.f * mid[mi][nj][3]);
        }
    }
    __syncthreads();
    {
        int row = tid >> 1;
        int cb2 = (tid & 1) * 16;
        int gc0 = nblk * 32 + cb2;
        const float* bgp = bg + (size_t)e * HID + gc0;
        const float* bip = bi + (size_t)e * HID + gc0;
        float* hout = g_h + (size_t)(mtile * TMR + row) * HID + gc0;
        float lmax = 0.f;
        #pragma unroll
        for (int j4 = 0; j4 < 16; j4 += 4) {
            float4 hv;
            float* hp = (float*)&hv;
            #pragma unroll
            for (int q = 0; q < 4; q++) {
                int lc = cb2 + j4 + q;
                float gval = S[row * 66 + lc] + bgp[j4 + q];
                float ival = S[row * 66 + 32 + lc] + bip[j4 + q];
                float hvv = (gval / (1.0f + __expf(-gval))) * ival;
                hp[q] = hvv;
                lmax = fmaxf(lmax, fabsf(hvv));
            }
            *(float4*)(hout + j4) = hv;
        }
        atomicMax(&g_sh_bits[mtile * TMR + row], __float_as_int(lmax));
    }
}

// ---------------------------------------------------------------------------
// down GEMM: A = hq [128 x 3072], B = wo^T block [64 x 3072]; scatter out
// ---------------------------------------------------------------------------
__global__ __launch_bounds__(256, 1)
void down_gemm_kernel(const float* __restrict__ bo, float* __restrict__ out)
{
    extern __shared__ char smem[];
    int mtile = blockIdx.x;
    int e = g_tile_expert[mtile];
    if (e < 0) return;
    int nblk = blockIdx.y;
    int N0 = nblk * 64;
    int tid = threadIdx.x, lane = tid & 31, wid = tid >> 5;
    int wm = wid >> 1, wn = wid & 1;

    int hh[2][4][4] = {}, mid[2][4][4] = {};
    run_mainloop<HID>(
        g_hq_hi + (size_t)mtile * TMR * HID, g_hq_lo + (size_t)mtile * TMR * HID,
        g_wo_hi + ((size_t)e * CDIM + N0) * HID, g_wo_lo + ((size_t)e * CDIM + N0) * HID,
        smem, tid, hh, mid);

    const float INVQ = 1.0f / QMAX;
    #pragma unroll
    for (int mi = 0; mi < 2; mi++) {
        int r0 = wm * 32 + mi * 16 + (lane >> 2);
        int p0 = g_perm[mtile * TMR + r0];
        int p1 = g_perm[mtile * TMR + r0 + 8];
        float sa0 = fmaxf(__int_as_float(g_sh_bits[mtile * TMR + r0]), 1e-30f) * INVQ;
        float sa1 = fmaxf(__int_as_float(g_sh_bits[mtile * TMR + r0 + 8]), 1e-30f) * INVQ;
        #pragma unroll
        for (int nj = 0; nj < 4; nj++) {
            int gcol = N0 + wn * 32 + nj * 8 + 2 * (lane & 3);
            float sb0 = g_swo[e * CDIM + gcol];
            float sb1 = g_swo[e * CDIM + gcol + 1];
            float b0 = bo[(size_t)e * CDIM + gcol];
            float b1 = bo[(size_t)e * CDIM + gcol + 1];
            if (p0 >= 0) {
                float v0 = sa0 * sb0 * (16384.f * hh[mi][nj][0] + 128.f * mid[mi][nj][0]) + b0;
                float v1 = sa0 * sb1 * (16384.f * hh[mi][nj][1] + 128.f * mid[mi][nj][1]) + b1;
                *(float2*)&out[(size_t)p0 * CDIM + gcol] = make_float2(v0, v1);
            }
            if (p1 >= 0) {
                float v2 = sa1 * sb0 * (16384.f * hh[mi][nj][2] + 128.f * mid[mi][nj][2]) + b0;
                float v3 = sa1 * sb1 * (16384.f * hh[mi][nj][3] + 128.f * mid[mi][nj][3]) + b1;
                *(float2*)&out[(size_t)p1 * CDIM + gcol] = make_float2(v2, v3);
            }
        }
    }
}

// ---------------------------------------------------------------------------
extern "C" void kernel_launch(void* const* d_in, const int* in_sizes, int n_in,
                              void* d_out, int out_size)
{
    const float* x      = (const float*)d_in[0];
    const int*   mapped = (const int*)  d_in[1];
    const float* Wg     = (const float*)d_in[2];
    const float* bg     = (const float*)d_in[3];
    const float* Wi     = (const float*)d_in[4];
    const float* bi     = (const float*)d_in[5];
    const float* Wo     = (const float*)d_in[6];
    const float* bo     = (const float*)d_in[7];
    float* out = (float*)d_out;

    route_kernel<<<1, 256>>>(mapped);
    quant_x_kernel<<<PADN, 256>>>(x);
    quant_wup_kernel<<<dim3(96, NEXP, 2), 256>>>(Wg, Wi);
    quant_wo_kernel<<<dim3(24, NEXP), 256>>>(Wo);

    up_gemm_kernel<<<dim3(MTILES, NUP / 64), 256, SMEM_UP>>>(bg, bi);
    quant_h_kernel<<<PADN, 256>>>();
    down_gemm_kernel<<<dim3(MTILES, CDIM / 64), 256, SMEM_LOOP>>>(bo, out);
}

// round 5
// speedup vs baseline: 2.5347x; 2.5347x over previous
#include <cuda_runtime.h>
#include <cuda_bf16.h>
#include <math.h>
#include <cstdint>

#define NTOK 4096
#define NEXP 8
#define CDIM 768
#define HID  3072
#define TM   128
#define PADN (NTOK + NEXP * TM)   // 5120
#define MTILES (PADN / TM)        // 40

// SMEM: A [128 rows][pitch 144B (32 tf32 + pad)] = 18432
//       B [32 k][pitch 528B (128 tf32 + pad)]   = 16896  -> 35328 mainloop
//       up epilogue staging 128x132 fp32        = 67584
#define SB_OFF 18432
#define APITCH 144
#define BPITCH 528
#define SMEM_DN 35328
#define SMEM_UP 67584

// ---------------- scratch ----------------
__device__ int g_perm[PADN];
__device__ int g_tile_expert[MTILES];
__device__ __align__(128) float g_xr[(size_t)PADN * CDIM];           // 15.7 MB
__device__ __align__(128) float g_h[(size_t)PADN * HID];             // 62.9 MB
__device__ __align__(128) float g_wg_r[(size_t)NEXP * CDIM * HID];   // 75.5 MB
__device__ __align__(128) float g_wi_r[(size_t)NEXP * CDIM * HID];   // 75.5 MB
__device__ __align__(128) float g_wo_r[(size_t)NEXP * HID * CDIM];   // 75.5 MB

// ---------------- helpers ----------------
static __device__ __forceinline__ uint32_t smem_u32(const void* p) {
    uint32_t a;
    asm("{ .reg .u64 t; cvta.to.shared.u64 t, %1; cvt.u32.u64 %0, t; }" : "=r"(a) : "l"(p));
    return a;
}
static __device__ __forceinline__ float tf32r(float x) {
    uint32_t u;
    asm("cvt.rna.tf32.f32 %0, %1;" : "=r"(u) : "f"(x));
    return __uint_as_float(u);
}
static __device__ __forceinline__ void ldsm4(uint32_t* r, uint32_t a) {
    asm volatile("ldmatrix.sync.aligned.m8n8.x4.shared.b16 {%0,%1,%2,%3}, [%4];"
        : "=r"(r[0]), "=r"(r[1]), "=r"(r[2]), "=r"(r[3]) : "r"(a));
}
static __device__ __forceinline__ void mma_tf32(float* c, const uint32_t* a,
                                                uint32_t b0, uint32_t b1) {
    asm volatile("mma.sync.aligned.m16n8k8.row.col.f32.tf32.tf32.f32 "
        "{%0,%1,%2,%3}, {%4,%5,%6,%7}, {%8,%9}, {%0,%1,%2,%3};"
        : "+f"(c[0]), "+f"(c[1]), "+f"(c[2]), "+f"(c[3])
        : "r"(a[0]), "r"(a[1]), "r"(a[2]), "r"(a[3]), "r"(b0), "r"(b1));
}

// ---------------------------------------------------------------------------
// route
// ---------------------------------------------------------------------------
__global__ void route_kernel(const int* __restrict__ mapped) {
    __shared__ int cnt[NEXP];
    __shared__ int off[NEXP];
    __shared__ int fill[NEXP];
    int tid = threadIdx.x;
    if (tid < NEXP) { cnt[tid] = 0; fill[tid] = 0; }
    __syncthreads();
    for (int i = tid; i < NTOK; i += blockDim.x) atomicAdd(&cnt[mapped[i]], 1);
    __syncthreads();
    if (tid == 0) {
        int o = 0;
        for (int e = 0; e < NEXP; e++) {
            off[e] = o;
            int tiles = (cnt[e] + TM - 1) / TM;
            for (int t = 0; t < tiles; t++) g_tile_expert[o / TM + t] = e;
            o += tiles * TM;
        }
        for (int t = o / TM; t < MTILES; t++) g_tile_expert[t] = -1;
    }
    __syncthreads();
    for (int i = tid; i < PADN; i += blockDim.x) g_perm[i] = -1;
    __syncthreads();
    for (int i = tid; i < NTOK; i += blockDim.x) {
        int e = mapped[i];
        g_perm[off[e] + atomicAdd(&fill[e], 1)] = i;
    }
}

// ---------------------------------------------------------------------------
// prep_w: round all expert weights to canonical tf32 (one bandwidth pass)
// ---------------------------------------------------------------------------
__global__ __launch_bounds__(256) void prep_w_kernel(
    const float* __restrict__ Wg, const float* __restrict__ Wi,
    const float* __restrict__ Wo)
{
    int m = blockIdx.y;
    const float* src = (m == 0) ? Wg : (m == 1) ? Wi : Wo;
    float* dst = (m == 0) ? g_wg_r : (m == 1) ? g_wi_r : g_wo_r;
    size_t base = ((size_t)blockIdx.x * 256 + threadIdx.x) * 4;  // float4 index
    const float4* s4 = (const float4*)src + base;
    float4* d4 = (float4*)dst + base;
    #pragma unroll
    for (int i = 0; i < 4; i++) {
        float4 v = s4[i];
        v.x = tf32r(v.x); v.y = tf32r(v.y); v.z = tf32r(v.z); v.w = tf32r(v.w);
        d4[i] = v;
    }
}

// ---------------------------------------------------------------------------
// prep_x: gather-permute x rows + round to tf32 (pad rows -> 0)
// ---------------------------------------------------------------------------
__global__ __launch_bounds__(256) void prep_x_kernel(const float* __restrict__ x) {
    int row = blockIdx.x, tid = threadIdx.x;
    int prow = g_perm[row];
    const float* xr = (prow >= 0) ? x + (size_t)prow * CDIM : nullptr;
    #pragma unroll
    for (int j = 0; j < 3; j++) {
        int i = tid + 256 * j;
        float v = xr ? xr[i] : 0.0f;
        g_xr[(size_t)row * CDIM + i] = tf32r(v);
    }
}

// ---------------------------------------------------------------------------
// up GEMM: [128 tok] x [Wg 64 | Wi 64 cols], K=768, single-pass tf32 mma
// ---------------------------------------------------------------------------
__global__ __launch_bounds__(256, 2) void up_gemm(
    const float* __restrict__ bg, const float* __restrict__ bi)
{
    extern __shared__ char smem[];
    int mtile = blockIdx.x;
    int e = g_tile_expert[mtile];
    if (e < 0) return;
    int gn0 = blockIdx.y * 64;
    int tid = threadIdx.x, lane = tid & 31, wid = tid >> 5;
    int wm = wid >> 2, wn = wid & 3;
    uint32_t sb = smem_u32(smem);

    // A loader: row = tid>>1, 16 floats at kc=(tid&1)*16
    const float* pA = g_xr + (size_t)(mtile * TM + (tid >> 1)) * CDIM + (tid & 1) * 16;
    int aoff = (tid >> 1) * APITCH + (tid & 1) * 64;
    // B loader: threads<128 -> Wg (n 0-63), >=128 -> Wi (n 64-127)
    int tl = tid & 127;
    const float* pB = ((tid < 128) ? g_wg_r : g_wi_r) + (size_t)e * CDIM * HID
                    + (size_t)(tl >> 2) * HID + gn0 + (tl & 3) * 16;
    int boff = SB_OFF + (tl >> 2) * BPITCH + ((tid < 128) ? 0 : 256) + (tl & 3) * 64;

    float4 ra[4], rb[4];
    #pragma unroll
    for (int i = 0; i < 4; i++) { ra[i] = ((const float4*)pA)[i]; rb[i] = ((const float4*)pB)[i]; }

    float acc[4][4][4] = {};
    int l7 = lane & 7, lb8 = ((lane >> 3) & 1) * 8, lh = lane >> 4;
    int a_lane = (l7 + lb8) * APITCH + lh * 16;
    int bk = lane & 3, bn = (lane >> 2) * 4;

    for (int s = 0; s < 24; s++) {
        __syncthreads();
        #pragma unroll
        for (int i = 0; i < 4; i++) {
            *(float4*)(smem + aoff + i * 16) = ra[i];
            *(float4*)(smem + boff + i * 16) = rb[i];
        }
        __syncthreads();
        if (s < 23) {
            const float4* nA = (const float4*)(pA + (s + 1) * 32);
            const float4* nB = (const float4*)(pB + (size_t)(s + 1) * 32 * HID);
            #pragma unroll
            for (int i = 0; i < 4; i++) { ra[i] = nA[i]; rb[i] = nB[i]; }
        }
        #pragma unroll
        for (int c = 0; c < 4; c++) {
            uint32_t a[4][4];
            #pragma unroll
            for (int mi = 0; mi < 4; mi++)
                ldsm4(a[mi], sb + (wm * 64 + mi * 16) * APITCH + a_lane + c * 32);
            uint32_t b0[4], b1[4];
            int kb = SB_OFF + (c * 8 + bk) * BPITCH + wn * 128 + bn;
            #pragma unroll
            for (int nj = 0; nj < 4; nj++) {
                b0[nj] = *(const uint32_t*)(smem + kb + nj * 32);
                b1[nj] = *(const uint32_t*)(smem + kb + 4 * BPITCH + nj * 32);
            }
            #pragma unroll
            for (int mi = 0; mi < 4; mi++)
                #pragma unroll
                for (int nj = 0; nj < 4; nj++)
                    mma_tf32(acc[mi][nj], a[mi], b0[nj], b1[nj]);
        }
    }

    // epilogue: stage, pair G/I, SiLU, round to tf32, store h
    __syncthreads();
    float* S = (float*)smem;
    int g = lane >> 2, tq = lane & 3;
    #pragma unroll
    for (int mi = 0; mi < 4; mi++) {
        int r0 = wm * 64 + mi * 16 + g;
        #pragma unroll
        for (int nj = 0; nj < 4; nj++) {
            int col = wn * 32 + nj * 8 + 2 * tq;
            S[r0 * 132 + col]           = acc[mi][nj][0];
            S[r0 * 132 + col + 1]       = acc[mi][nj][1];
            S[(r0 + 8) * 132 + col]     = acc[mi][nj][2];
            S[(r0 + 8) * 132 + col + 1] = acc[mi][nj][3];
        }
    }
    __syncthreads();
    {
        int row = tid >> 1, cb = (tid & 1) * 32;
        const float* bgp = bg + (size_t)e * HID + gn0;
        const float* bip = bi + (size_t)e * HID + gn0;
        float* hp = g_h + (size_t)(mtile * TM + row) * HID + gn0 + cb;
        #pragma unroll
        for (int j0 = 0; j0 < 32; j0 += 4) {
            float4 o;
            float* op = (float*)&o;
            #pragma unroll
            for (int q = 0; q < 4; q++) {
                int c = cb + j0 + q;
                float gv = S[row * 132 + c] + bgp[c];
                float iv = S[row * 132 + 64 + c] + bip[c];
                op[q] = tf32r((gv / (1.0f + __expf(-gv))) * iv);
            }
            *(float4*)(hp + j0) = o;
        }
    }
}

// ---------------------------------------------------------------------------
// down GEMM: y = h @ Wo + bo, K=3072, BN=128, scatter via perm
// ---------------------------------------------------------------------------
__global__ __launch_bounds__(256, 2) void down_gemm(
    const float* __restrict__ bo, float* __restrict__ out)
{
    extern __shared__ char smem[];
    int mtile = blockIdx.x;
    int e = g_tile_expert[mtile];
    if (e < 0) return;
    int gn0 = blockIdx.y * 128;
    int tid = threadIdx.x, lane = tid & 31, wid = tid >> 5;
    int wm = wid >> 2, wn = wid & 3;
    uint32_t sb = smem_u32(smem);

    const float* pA = g_h + (size_t)(mtile * TM + (tid >> 1)) * HID + (tid & 1) * 16;
    int aoff = (tid >> 1) * APITCH + (tid & 1) * 64;
    const float* pB = g_wo_r + (size_t)e * HID * CDIM
                    + (size_t)(tid >> 3) * CDIM + gn0 + (tid & 7) * 16;
    int boff = SB_OFF + (tid >> 3) * BPITCH + (tid & 7) * 64;

    float4 ra[4], rb[4];
    #pragma unroll
    for (int i = 0; i < 4; i++) { ra[i] = ((const float4*)pA)[i]; rb[i] = ((const float4*)pB)[i]; }

    float acc[4][4][4] = {};
    int l7 = lane & 7, lb8 = ((lane >> 3) & 1) * 8, lh = lane >> 4;
    int a_lane = (l7 + lb8) * APITCH + lh * 16;
    int bk = lane & 3, bn = (lane >> 2) * 4;

    for (int s = 0; s < 96; s++) {
        __syncthreads();
        #pragma unroll
        for (int i = 0; i < 4; i++) {
            *(float4*)(smem + aoff + i * 16) = ra[i];
            *(float4*)(smem + boff + i * 16) = rb[i];
        }
        __syncthreads();
        if (s < 95) {
            const float4* nA = (const float4*)(pA + (s + 1) * 32);
            const float4* nB = (const float4*)(pB + (size_t)(s + 1) * 32 * CDIM);
            #pragma unroll
            for (int i = 0; i < 4; i++) { ra[i] = nA[i]; rb[i] = nB[i]; }
        }
        #pragma unroll
        for (int c = 0; c < 4; c++) {
            uint32_t a[4][4];
            #pragma unroll
            for (int mi = 0; mi < 4; mi++)
                ldsm4(a[mi], sb + (wm * 64 + mi * 16) * APITCH + a_lane + c * 32);
            uint32_t b0[4], b1[4];
            int kb = SB_OFF + (c * 8 + bk) * BPITCH + wn * 128 + bn;
            #pragma unroll
            for (int nj = 0; nj < 4; nj++) {
                b0[nj] = *(const uint32_t*)(smem + kb + nj * 32);
                b1[nj] = *(const uint32_t*)(smem + kb + 4 * BPITCH + nj * 32);
            }
            #pragma unroll
            for (int mi = 0; mi < 4; mi++)
                #pragma unroll
                for (int nj = 0; nj < 4; nj++)
                    mma_tf32(acc[mi][nj], a[mi], b0[nj], b1[nj]);
        }
    }

    // epilogue: bias + scatter directly from regs
    int g = lane >> 2, tq = lane & 3;
    const float* bop = bo + (size_t)e * CDIM;
    #pragma unroll
    for (int mi = 0; mi < 4; mi++) {
        int r0 = wm * 64 + mi * 16 + g;
        int p0 = g_perm[mtile * TM + r0];
        int p1 = g_perm[mtile * TM + r0 + 8];
        #pragma unroll
        for (int nj = 0; nj < 4; nj++) {
            int col = gn0 + wn * 32 + nj * 8 + 2 * tq;
            float2 b = *(const float2*)(bop + col);
            if (p0 >= 0)
                *(float2*)&out[(size_t)p0 * CDIM + col] =
                    make_float2(acc[mi][nj][0] + b.x, acc[mi][nj][1] + b.y);
            if (p1 >= 0)
                *(float2*)&out[(size_t)p1 * CDIM + col] =
                    make_float2(acc[mi][nj][2] + b.x, acc[mi][nj][3] + b.y);
        }
    }
}

// ---------------------------------------------------------------------------
extern "C" void kernel_launch(void* const* d_in, const int* in_sizes, int n_in,
                              void* d_out, int out_size)
{
    const float* x      = (const float*)d_in[0];
    const int*   mapped = (const int*)  d_in[1];
    const float* Wg     = (const float*)d_in[2];
    const float* bg     = (const float*)d_in[3];
    const float* Wi     = (const float*)d_in[4];
    const float* bi     = (const float*)d_in[5];
    const float* Wo     = (const float*)d_in[6];
    const float* bo     = (const float*)d_in[7];
    float* out = (float*)d_out;

    cudaFuncSetAttribute(up_gemm,   cudaFuncAttributeMaxDynamicSharedMemorySize, SMEM_UP);
    cudaFuncSetAttribute(down_gemm, cudaFuncAttributeMaxDynamicSharedMemorySize, SMEM_DN);

    route_kernel<<<1, 256>>>(mapped);
    prep_x_kernel<<<PADN, 256>>>(x);
    prep_w_kernel<<<dim3(4608, 3), 256>>>(Wg, Wi, Wo);  // 4608*256*16 = 18.87M floats each

    up_gemm<<<dim3(MTILES, HID / 64), 256, SMEM_UP>>>(bg, bi);      // 40 x 48
    down_gemm<<<dim3(MTILES, CDIM / 128), 256, SMEM_DN>>>(bo, out); // 40 x 6
}

// round 7
// speedup vs baseline: 2.8488x; 1.1239x over previous
#include <cuda_runtime.h>
#include <cuda_bf16.h>
#include <math.h>
#include <cstdint>

#define NTOK 4096
#define NEXP 8
#define CDIM 768
#define HID  3072
#define TM   128
#define PADN (NTOK + NEXP * TM)   // 5120
#define MTILES (PADN / TM)        // 40

// Stage: A [128 rows][pitch 144B] = 18432 ; B [32 k][pitch 544B] = 17408
#define APITCH 144
#define BPITCH 544                // 136 floats: B scalar loads bank-conflict-free
#define SB_OFF 18432
#define SSZ    35840              // one stage (A + B)
#define SMEM_SZ 71680             // two stages; >= 67584 up-epilogue staging

// ---------------- scratch ----------------
__device__ int g_perm[PADN];
__device__ int g_tile_expert[MTILES];
__device__ __align__(128) float g_xr[(size_t)PADN * CDIM];
__device__ __align__(128) float g_h[(size_t)PADN * HID];
__device__ __align__(128) float g_wg_r[(size_t)NEXP * CDIM * HID];
__device__ __align__(128) float g_wi_r[(size_t)NEXP * CDIM * HID];
__device__ __align__(128) float g_wo_r[(size_t)NEXP * HID * CDIM];

// ---------------- helpers ----------------
static __device__ __forceinline__ uint32_t smem_u32(const void* p) {
    uint32_t a;
    asm("{ .reg .u64 t; cvta.to.shared.u64 t, %1; cvt.u32.u64 %0, t; }" : "=r"(a) : "l"(p));
    return a;
}
static __device__ __forceinline__ float tf32r(float x) {
    uint32_t u;
    asm("cvt.rna.tf32.f32 %0, %1;" : "=r"(u) : "f"(x));
    return __uint_as_float(u);
}
static __device__ __forceinline__ void ldsm4(uint32_t* r, uint32_t a) {
    asm volatile("ldmatrix.sync.aligned.m8n8.x4.shared.b16 {%0,%1,%2,%3}, [%4];"
        : "=r"(r[0]), "=r"(r[1]), "=r"(r[2]), "=r"(r[3]) : "r"(a));
}
static __device__ __forceinline__ void mma_tf32(float* c, const uint32_t* a,
                                                uint32_t b0, uint32_t b1) {
    asm volatile("mma.sync.aligned.m16n8k8.row.col.f32.tf32.tf32.f32 "
        "{%0,%1,%2,%3}, {%4,%5,%6,%7}, {%8,%9}, {%0,%1,%2,%3};"
        : "+f"(c[0]), "+f"(c[1]), "+f"(c[2]), "+f"(c[3])
        : "r"(a[0]), "r"(a[1]), "r"(a[2]), "r"(a[3]), "r"(b0), "r"(b1));
}

// ---------------------------------------------------------------------------
// route
// ---------------------------------------------------------------------------
__global__ void route_kernel(const int* __restrict__ mapped) {
    __shared__ int cnt[NEXP];
    __shared__ int off[NEXP];
    __shared__ int fill[NEXP];
    int tid = threadIdx.x;
    if (tid < NEXP) { cnt[tid] = 0; fill[tid] = 0; }
    __syncthreads();
    for (int i = tid; i < NTOK; i += blockDim.x) atomicAdd(&cnt[mapped[i]], 1);
    __syncthreads();
    if (tid == 0) {
        int o = 0;
        for (int e = 0; e < NEXP; e++) {
            off[e] = o;
            int tiles = (cnt[e] + TM - 1) / TM;
            for (int t = 0; t < tiles; t++) g_tile_expert[o / TM + t] = e;
            o += tiles * TM;
        }
        for (int t = o / TM; t < MTILES; t++) g_tile_expert[t] = -1;
    }
    __syncthreads();
    for (int i = tid; i < PADN; i += blockDim.x) g_perm[i] = -1;
    __syncthreads();
    for (int i = tid; i < NTOK; i += blockDim.x) {
        int e = mapped[i];
        g_perm[off[e] + atomicAdd(&fill[e], 1)] = i;
    }
}

// ---------------------------------------------------------------------------
// prep_w: round all expert weights to canonical tf32 (one bandwidth pass)
// ---------------------------------------------------------------------------
__global__ __launch_bounds__(256) void prep_w_kernel(
    const float* __restrict__ Wg, const float* __restrict__ Wi,
    const float* __restrict__ Wo)
{
    int m = blockIdx.y;
    const float* src = (m == 0) ? Wg : (m == 1) ? Wi : Wo;
    float* dst = (m == 0) ? g_wg_r : (m == 1) ? g_wi_r : g_wo_r;
    size_t base = ((size_t)blockIdx.x * 256 + threadIdx.x) * 4;
    const float4* s4 = (const float4*)src + base;
    float4* d4 = (float4*)dst + base;
    #pragma unroll
    for (int i = 0; i < 4; i++) {
        float4 v = s4[i];
        v.x = tf32r(v.x); v.y = tf32r(v.y); v.z = tf32r(v.z); v.w = tf32r(v.w);
        d4[i] = v;
    }
}

// ---------------------------------------------------------------------------
// prep_x: gather-permute x rows + round to tf32 (pad rows -> 0)
// ---------------------------------------------------------------------------
__global__ __launch_bounds__(256) void prep_x_kernel(const float* __restrict__ x) {
    int row = blockIdx.x, tid = threadIdx.x;
    int prow = g_perm[row];
    const float* xr = (prow >= 0) ? x + (size_t)prow * CDIM : nullptr;
    #pragma unroll
    for (int j = 0; j < 3; j++) {
        int i = tid + 256 * j;
        float v = xr ? xr[i] : 0.0f;
        g_xr[(size_t)row * CDIM + i] = tf32r(v);
    }
}

// ---------------------------------------------------------------------------
// up GEMM: [128 tok] x [Wg 64 | Wi 64 cols], K=768, double-buffered
// ---------------------------------------------------------------------------
__global__ __launch_bounds__(256, 2) void up_gemm(
    const float* __restrict__ bg, const float* __restrict__ bi)
{
    extern __shared__ char smem[];
    int mtile = blockIdx.x;
    int e = g_tile_expert[mtile];
    if (e < 0) return;
    int gn0 = blockIdx.y * 64;
    int tid = threadIdx.x, lane = tid & 31, wid = tid >> 5;
    int wm = wid >> 2, wn = wid & 3;
    uint32_t sb = smem_u32(smem);

    const float* pA = g_xr + (size_t)(mtile * TM + (tid >> 1)) * CDIM + (tid & 1) * 16;
    int aoff = (tid >> 1) * APITCH + (tid & 1) * 64;
    int tl = tid & 127;
    const float* pB = ((tid < 128) ? g_wg_r : g_wi_r) + (size_t)e * CDIM * HID
                    + (size_t)(tl >> 2) * HID + gn0 + (tl & 3) * 16;
    int boff = SB_OFF + (tl >> 2) * BPITCH + ((tid < 128) ? 0 : 256) + (tl & 3) * 64;

    float4 ra[4], rb[4];
    #pragma unroll
    for (int i = 0; i < 4; i++) { ra[i] = ((const float4*)pA)[i]; rb[i] = ((const float4*)pB)[i]; }
    #pragma unroll
    for (int i = 0; i < 4; i++) {
        *(float4*)(smem + aoff + i * 16) = ra[i];
        *(float4*)(smem + boff + i * 16) = rb[i];
    }
    __syncthreads();

    float acc[4][4][4] = {};
    int l7 = lane & 7, lb8 = ((lane >> 3) & 1) * 8, lh = lane >> 4;
    int a_lane = (l7 + lb8) * APITCH + lh * 16;
    int bk = lane & 3, bn = (lane >> 2) * 4;

    for (int s = 0; s < 24; s++) {
        int cso = (s & 1) * SSZ;
        if (s < 23) {
            const float4* nA = (const float4*)(pA + (s + 1) * 32);
            const float4* nB = (const float4*)(pB + (size_t)(s + 1) * 32 * HID);
            #pragma unroll
            for (int i = 0; i < 4; i++) { ra[i] = nA[i]; rb[i] = nB[i]; }
        }
        #pragma unroll
        for (int c = 0; c < 4; c++) {
            uint32_t a[4][4];
            #pragma unroll
            for (int mi = 0; mi < 4; mi++)
                ldsm4(a[mi], sb + cso + (wm * 64 + mi * 16) * APITCH + a_lane + c * 32);
            uint32_t b0[4], b1[4];
            int kb = cso + SB_OFF + (c * 8 + bk) * BPITCH + wn * 128 + bn;
            #pragma unroll
            for (int nj = 0; nj < 4; nj++) {
                b0[nj] = *(const uint32_t*)(smem + kb + nj * 32);
                b1[nj] = *(const uint32_t*)(smem + kb + 4 * BPITCH + nj * 32);
            }
            #pragma unroll
            for (int mi = 0; mi < 4; mi++)
                #pragma unroll
                for (int nj = 0; nj < 4; nj++)
                    mma_tf32(acc[mi][nj], a[mi], b0[nj], b1[nj]);
        }
        if (s < 23) {
            int nso = ((s + 1) & 1) * SSZ;
            #pragma unroll
            for (int i = 0; i < 4; i++) {
                *(float4*)(smem + nso + aoff + i * 16) = ra[i];
                *(float4*)(smem + nso + boff + i * 16) = rb[i];
            }
        }
        __syncthreads();
    }

    // epilogue: stage, pair G/I, SiLU, round to tf32, store h
    float* S = (float*)smem;
    int g = lane >> 2, tq = lane & 3;
    #pragma unroll
    for (int mi = 0; mi < 4; mi++) {
        int r0 = wm * 64 + mi * 16 + g;
        #pragma unroll
        for (int nj = 0; nj < 4; nj++) {
            int col = wn * 32 + nj * 8 + 2 * tq;
            S[r0 * 132 + col]           = acc[mi][nj][0];
            S[r0 * 132 + col + 1]       = acc[mi][nj][1];
            S[(r0 + 8) * 132 + col]     = acc[mi][nj][2];
            S[(r0 + 8) * 132 + col + 1] = acc[mi][nj][3];
        }
    }
    __syncthreads();
    {
        int row = tid >> 1, cb = (tid & 1) * 32;
        const float* bgp = bg + (size_t)e * HID + gn0;
        const float* bip = bi + (size_t)e * HID + gn0;
        float* hp = g_h + (size_t)(mtile * TM + row) * HID + gn0 + cb;
        #pragma unroll
        for (int j0 = 0; j0 < 32; j0 += 4) {
            float4 o;
            float* op = (float*)&o;
            #pragma unroll
            for (int q = 0; q < 4; q++) {
                int c = cb + j0 + q;
                float gv = S[row * 132 + c] + bgp[c];
                float iv = S[row * 132 + 64 + c] + bip[c];
                op[q] = tf32r((gv / (1.0f + __expf(-gv))) * iv);
            }
            *(float4*)(hp + j0) = o;
        }
    }
}

// ---------------------------------------------------------------------------
// down GEMM: y = h @ Wo + bo, K=3072, BN=128, double-buffered, scatter
// ---------------------------------------------------------------------------
__global__ __launch_bounds__(256, 2) void down_gemm(
    const float* __restrict__ bo, float* __restrict__ out)
{
    extern __shared__ char smem[];
    int mtile = blockIdx.x;
    int e = g_tile_expert[mtile];
    if (e < 0) return;
    int gn0 = blockIdx.y * 128;
    int tid = threadIdx.x, lane = tid & 31, wid = tid >> 5;
    int wm = wid >> 2, wn = wid & 3;
    uint32_t sb = smem_u32(smem);

    const float* pA = g_h + (size_t)(mtile * TM + (tid >> 1)) * HID + (tid & 1) * 16;
    int aoff = (tid >> 1) * APITCH + (tid & 1) * 64;
    const float* pB = g_wo_r + (size_t)e * HID * CDIM
                    + (size_t)(tid >> 3) * CDIM + gn0 + (tid & 7) * 16;
    int boff = SB_OFF + (tid >> 3) * BPITCH + (tid & 7) * 64;

    float4 ra[4], rb[4];
    #pragma unroll
    for (int i = 0; i < 4; i++) { ra[i] = ((const float4*)pA)[i]; rb[i] = ((const float4*)pB)[i]; }
    #pragma unroll
    for (int i = 0; i < 4; i++) {
        *(float4*)(smem + aoff + i * 16) = ra[i];
        *(float4*)(smem + boff + i * 16) = rb[i];
    }
    __syncthreads();

    float acc[4][4][4] = {};
    int l7 = lane & 7, lb8 = ((lane >> 3) & 1) * 8, lh = lane >> 4;
    int a_lane = (l7 + lb8) * APITCH + lh * 16;
    int bk = lane & 3, bn = (lane >> 2) * 4;

    for (int s = 0; s < 96; s++) {
        int cso = (s & 1) * SSZ;
        if (s < 95) {
            const float4* nA = (const float4*)(pA + (s + 1) * 32);
            const float4* nB = (const float4*)(pB + (size_t)(s + 1) * 32 * CDIM);
            #pragma unroll
            for (int i = 0; i < 4; i++) { ra[i] = nA[i]; rb[i] = nB[i]; }
        }
        #pragma unroll
        for (int c = 0; c < 4; c++) {
            uint32_t a[4][4];
            #pragma unroll
            for (int mi = 0; mi < 4; mi++)
                ldsm4(a[mi], sb + cso + (wm * 64 + mi * 16) * APITCH + a_lane + c * 32);
            uint32_t b0[4], b1[4];
            int kb = cso + SB_OFF + (c * 8 + bk) * BPITCH + wn * 128 + bn;
            #pragma unroll
            for (int nj = 0; nj < 4; nj++) {
                b0[nj] = *(const uint32_t*)(smem + kb + nj * 32);
                b1[nj] = *(const uint32_t*)(smem + kb + 4 * BPITCH + nj * 32);
            }
            #pragma unroll
            for (int mi = 0; mi < 4; mi++)
                #pragma unroll
                for (int nj = 0; nj < 4; nj++)
                    mma_tf32(acc[mi][nj], a[mi], b0[nj], b1[nj]);
        }
        if (s < 95) {
            int nso = ((s + 1) & 1) * SSZ;
            #pragma unroll
            for (int i = 0; i < 4; i++) {
                *(float4*)(smem + nso + aoff + i * 16) = ra[i];
                *(float4*)(smem + nso + boff + i * 16) = rb[i];
            }
        }
        __syncthreads();
    }

    // epilogue: bias + scatter directly from regs
    int g = lane >> 2, tq = lane & 3;
    const float* bop = bo + (size_t)e * CDIM;
    #pragma unroll
    for (int mi = 0; mi < 4; mi++) {
        int r0 = wm * 64 + mi * 16 + g;
        int p0 = g_perm[mtile * TM + r0];
        int p1 = g_perm[mtile * TM + r0 + 8];
        #pragma unroll
        for (int nj = 0; nj < 4; nj++) {
            int col = gn0 + wn * 32 + nj * 8 + 2 * tq;
            float2 b = *(const float2*)(bop + col);
            if (p0 >= 0)
                *(float2*)&out[(size_t)p0 * CDIM + col] =
                    make_float2(acc[mi][nj][0] + b.x, acc[mi][nj][1] + b.y);
            if (p1 >= 0)
                *(float2*)&out[(size_t)p1 * CDIM + col] =
                    make_float2(acc[mi][nj][2] + b.x, acc[mi][nj][3] + b.y);
        }
    }
}

// ---------------------------------------------------------------------------
extern "C" void kernel_launch(void* const* d_in, const int* in_sizes, int n_in,
                              void* d_out, int out_size)
{
    const float* x      = (const float*)d_in[0];
    const int*   mapped = (const int*)  d_in[1];
    const float* Wg     = (const float*)d_in[2];
    const float* bg     = (const float*)d_in[3];
    const float* Wi     = (const float*)d_in[4];
    const float* bi     = (const float*)d_in[5];
    const float* Wo     = (const float*)d_in[6];
    const float* bo     = (const float*)d_in[7];
    float* out = (float*)d_out;

    cudaFuncSetAttribute(up_gemm,   cudaFuncAttributeMaxDynamicSharedMemorySize, SMEM_SZ);
    cudaFuncSetAttribute(down_gemm, cudaFuncAttributeMaxDynamicSharedMemorySize, SMEM_SZ);

    route_kernel<<<1, 256>>>(mapped);
    prep_x_kernel<<<PADN, 256>>>(x);
    prep_w_kernel<<<dim3(4608, 3), 256>>>(Wg, Wi, Wo);

    up_gemm<<<dim3(MTILES, HID / 64), 256, SMEM_SZ>>>(bg, bi);      // 40 x 48
    down_gemm<<<dim3(MTILES, CDIM / 128), 256, SMEM_SZ>>>(bo, out); // 40 x 6
}